// round 15
// baseline (speedup 1.0000x reference)
#include <cuda_runtime.h>
#include <cuda.h>
#include <math.h>

// Top2Router: x[16384,2048] fp32, W[8,2048], b[8]
// out (fp32 concat): top2_val[N*2] | top2_idx[N*2] | gate[N*8]
//
// R14 kernel (29.4us), single change: TMA tensor maps use
// CU_TENSOR_MAP_L2_PROMOTION_L2_256B. The two 128B-wide tiles per chunk are
// adjacent spans of each token row, so 256B promotion makes tile1 hit L2 and
// turns DRAM traffic into 256B contiguous touches (higher HBM efficiency).

#define D_MODEL  2048
#define NEXP     8
#define KCHUNK   64
#define NCHUNK   (D_MODEL / KCHUNK)   // 32
#define NSTAGE   5
#define THREADS  512
#define NWARP    16
#define HIPAD    112                   // layout rows per tile (mult of 8)
#define TILE_F   (32 * HIPAD)          // floats per tile  (3584)
#define STAGE_F  (2 * TILE_F)          // floats per stage (7168)

typedef unsigned long long u64;

__device__ __forceinline__ void mbar_init(unsigned mb, unsigned count) {
    asm volatile("mbarrier.init.shared.b64 [%0], %1;" :: "r"(mb), "r"(count) : "memory");
}
__device__ __forceinline__ void mbar_expect_tx(unsigned mb, unsigned bytes) {
    asm volatile("mbarrier.arrive.expect_tx.shared.b64 _, [%0], %1;"
                 :: "r"(mb), "r"(bytes) : "memory");
}
__device__ __forceinline__ void mbar_wait(unsigned mb, unsigned parity) {
    asm volatile(
        "{\n\t.reg .pred P;\n"
        "W_%=:\n\t"
        "mbarrier.try_wait.parity.acquire.cta.shared::cta.b64 P, [%0], %1, 0x989680;\n\t"
        "@P bra D_%=;\n\t"
        "bra W_%=;\n"
        "D_%=:\n\t}"
        :: "r"(mb), "r"(parity) : "memory");
}
__device__ __forceinline__ void tma2d(unsigned dst, const CUtensorMap* map,
                                      int c0, int c1, unsigned mb) {
    asm volatile(
        "cp.async.bulk.tensor.2d.shared::cta.global.tile.mbarrier::complete_tx::bytes "
        "[%0], [%1, {%2, %3}], [%4];"
        :: "r"(dst), "l"(map), "r"(c0), "r"(c1), "r"(mb) : "memory");
}

__global__ __launch_bounds__(THREADS, 1)
void top2_router_kernel(const __grid_constant__ CUtensorMap mapHi,
                        const __grid_constant__ CUtensorMap mapLo,
                        const float* __restrict__ W,
                        const float* __restrict__ b,
                        float* __restrict__ out,
                        int n_tok, int hi)
{
    extern __shared__ float smem[];
    float* ring = smem;                          // 5 * 7168 floats (aligned)
    float* wt   = smem + NSTAGE * STAGE_F;       // 16384 floats

    const unsigned smem_u32 = (unsigned)__cvta_generic_to_shared(smem);
    const unsigned ring_u32 = smem_u32;
    const unsigned mbar0    = smem_u32 + (unsigned)(NSTAGE * STAGE_F + 16384) * 4u;
    const unsigned stageBytes = (unsigned)STAGE_F * 4u;
    const unsigned tileBytes  = (unsigned)TILE_F * 4u;

    const int tid  = threadIdx.x;
    const int w    = tid >> 5;
    const int lane = tid & 31;

    // unit-1 balanced token range
    const int G     = gridDim.x;
    const int tokenBase = (int)(((long long)blockIdx.x       * n_tok) / G);
    const int tokenEnd  = (int)(((long long)(blockIdx.x + 1) * n_tok) / G);
    const int ntok_b    = tokenEnd - tokenBase;  // hi or hi-1

    const CUtensorMap* mp = (ntok_b == hi) ? &mapHi : &mapLo;
    const unsigned chunkBytes = (unsigned)ntok_b * 256u;   // 2 tiles * ntok_b * 128B

    // ---- FIRST: kick off TMA so DRAM is busy during W staging
    if (tid == 0) {
        #pragma unroll
        for (int s = 0; s < NSTAGE; ++s) mbar_init(mbar0 + s * 8, 1);
        asm volatile("fence.proxy.async.shared::cta;" ::: "memory");
        #pragma unroll
        for (int c = 0; c < 3; ++c) {
            unsigned mb  = mbar0 + (c % NSTAGE) * 8;
            unsigned dst = ring_u32 + (unsigned)(c % NSTAGE) * stageBytes;
            mbar_expect_tx(mb, chunkBytes);
            tma2d(dst,             mp, c * KCHUNK,      tokenBase, mb);
            tma2d(dst + tileBytes, mp, c * KCHUNK + 32, tokenBase, mb);
        }
    }

    // ---- stage W transposed: wt[k*8+e] = W[e*2048+k]
    #pragma unroll
    for (int i = 0; i < (D_MODEL * NEXP) / THREADS; ++i) {   // 32
        int idx = tid + i * THREADS;
        int e = idx >> 11;
        int k = idx & (D_MODEL - 1);
        wt[k * NEXP + e] = W[idx];
    }
    __syncthreads();

    // issue chunk 3 (slot 3 untouched; completes the 4-deep prologue)
    if (tid == 0) {
        unsigned mb  = mbar0 + 3 * 8;
        unsigned dst = ring_u32 + 3u * stageBytes;
        mbar_expect_tx(mb, chunkBytes);
        tma2d(dst,             mp, 3 * KCHUNK,      tokenBase, mb);
        tma2d(dst + tileBytes, mp, 3 * KCHUNK + 32, tokenBase, mb);
    }

    const u64* wt64 = reinterpret_cast<const u64*>(wt);

    u64 acc[4][4];
    #pragma unroll
    for (int t = 0; t < 4; ++t)
        #pragma unroll
        for (int p = 0; p < 4; ++p) acc[t][p] = 0ull;

    const int ws7    = w & 7;
    const int tsel   = (w >> 3);                 // tile 0/1 (k<32 / k>=32)
    const int tokLim = ntok_b - 1;

    for (int c = 0; c < NCHUNK; ++c) {
        mbar_wait(mbar0 + (c % NSTAGE) * 8, (unsigned)((c / NSTAGE) & 1));
        __syncthreads();   // all warps done chunk c-1 -> slot (c+4)%5 free

        if (tid == 0 && c + 4 < NCHUNK) {
            int cc = c + 4;
            unsigned mb  = mbar0 + (cc % NSTAGE) * 8;
            unsigned dst = ring_u32 + (unsigned)(cc % NSTAGE) * stageBytes;
            mbar_expect_tx(mb, chunkBytes);
            tma2d(dst,             mp, cc * KCHUNK,      tokenBase, mb);
            tma2d(dst + tileBytes, mp, cc * KCHUNK + 32, tokenBase, mb);
        }

        const float* tile = ring + (c % NSTAGE) * STAGE_F + tsel * TILE_F;

        float4 xv[4];
        #pragma unroll
        for (int t = 0; t < 4; ++t) {
            int tok = lane + t * 32;
            int tokc = tok > tokLim ? tokLim : tok;
            xv[t] = reinterpret_cast<const float4*>(tile + tokc * 32)
                        [ws7 ^ (tokc & 7)];
        }

        #pragma unroll
        for (int j = 0; j < 4; ++j) {
            int kg = c * KCHUNK + w * 4 + j;
            u64 wp0 = wt64[kg * 4 + 0];
            u64 wp1 = wt64[kg * 4 + 1];
            u64 wp2 = wt64[kg * 4 + 2];
            u64 wp3 = wt64[kg * 4 + 3];
            #pragma unroll
            for (int t = 0; t < 4; ++t) {
                float xk = (j == 0) ? xv[t].x : (j == 1) ? xv[t].y
                         : (j == 2) ? xv[t].z : xv[t].w;
                u64 xx;
                asm("mov.b64 %0, {%1, %1};" : "=l"(xx) : "f"(xk));
                asm("fma.rn.f32x2 %0, %1, %2, %0;" : "+l"(acc[t][0]) : "l"(xx), "l"(wp0));
                asm("fma.rn.f32x2 %0, %1, %2, %0;" : "+l"(acc[t][1]) : "l"(xx), "l"(wp1));
                asm("fma.rn.f32x2 %0, %1, %2, %0;" : "+l"(acc[t][2]) : "l"(xx), "l"(wp2));
                asm("fma.rn.f32x2 %0, %1, %2, %0;" : "+l"(acc[t][3]) : "l"(xx), "l"(wp3));
            }
        }
    }
    __syncthreads();

    // ---- cross-warp reduction (reuse ring)
    float2* red = reinterpret_cast<float2*>(ring);
    #pragma unroll
    for (int t = 0; t < 4; ++t) {
        int tok = lane + t * 32;
        #pragma unroll
        for (int p = 0; p < 4; ++p) {
            float lo, hv;
            asm("mov.b64 {%0, %1}, %2;" : "=f"(lo), "=f"(hv) : "l"(acc[t][p]));
            red[(w * 128 + tok) * 4 + p] = make_float2(lo, hv);
        }
    }
    __syncthreads();

    float* lgs = ring + 16384;
    {
        int tok = tid >> 2;
        int p   = tid & 3;
        float2 s = make_float2(0.f, 0.f);
        #pragma unroll
        for (int ww = 0; ww < NWARP; ++ww) {
            float2 v = red[(ww * 128 + tok) * 4 + p];
            s.x += v.x; s.y += v.y;
        }
        s.x += b[2 * p];
        s.y += b[2 * p + 1];
        reinterpret_cast<float2*>(lgs)[tok * 4 + p] = s;
    }
    __syncthreads();

    // ---- per-token softmax + stable top2
    if (tid < ntok_b) {
        const int g = tokenBase + tid;
        float gv[NEXP];
        float mx = -INFINITY;
        #pragma unroll
        for (int e = 0; e < NEXP; ++e) {
            gv[e] = lgs[tid * NEXP + e];
            mx = fmaxf(mx, gv[e]);
        }
        float ssum = 0.f;
        #pragma unroll
        for (int e = 0; e < NEXP; ++e) {
            gv[e] = __expf(gv[e] - mx);
            ssum += gv[e];
        }
        float inv = 1.f / ssum;
        #pragma unroll
        for (int e = 0; e < NEXP; ++e) gv[e] *= inv;

        float* gate_out = out + (size_t)n_tok * 4;
        float4 g0 = make_float4(gv[0], gv[1], gv[2], gv[3]);
        float4 g1 = make_float4(gv[4], gv[5], gv[6], gv[7]);
        *reinterpret_cast<float4*>(gate_out + (size_t)g * NEXP)     = g0;
        *reinterpret_cast<float4*>(gate_out + (size_t)g * NEXP + 4) = g1;

        int i1 = 0; float v1 = gv[0];
        #pragma unroll
        for (int e = 1; e < NEXP; ++e)
            if (gv[e] > v1) { v1 = gv[e]; i1 = e; }
        int i2 = -1; float v2 = -INFINITY;
        #pragma unroll
        for (int e = 0; e < NEXP; ++e)
            if (e != i1 && gv[e] > v2) { v2 = gv[e]; i2 = e; }

        *reinterpret_cast<float2*>(out + (size_t)g * 2) = make_float2(v1, v2);
        float* idx_out = out + (size_t)n_tok * 2;
        *reinterpret_cast<float2*>(idx_out + (size_t)g * 2) =
            make_float2((float)i1, (float)i2);
    }
}

// ---------------------------------------------------------------------------

typedef CUresult (*EncodeTiledFn)(
    CUtensorMap*, CUtensorMapDataType, cuuint32_t, void*,
    const cuuint64_t*, const cuuint64_t*, const cuuint32_t*, const cuuint32_t*,
    CUtensorMapInterleave, CUtensorMapSwizzle, CUtensorMapL2promotion,
    CUtensorMapFloatOOBfill);

static CUtensorMap g_mapHi, g_mapLo;
static const void* g_last_x = nullptr;
static int g_nsm = 0, g_hi = 0, g_smem = 0;

static void build_maps(const float* x, int n_tok, int hi, int lo)
{
    EncodeTiledFn enc = nullptr;
    cudaDriverEntryPointQueryResult qr;
    cudaGetDriverEntryPoint("cuTensorMapEncodeTiled", (void**)&enc,
                            cudaEnableDefault, &qr);
    cuuint64_t dims[2]    = {(cuuint64_t)D_MODEL, (cuuint64_t)n_tok};
    cuuint64_t strides[1] = {(cuuint64_t)D_MODEL * 4};
    cuuint32_t elem[2]    = {1, 1};
    cuuint32_t boxH[2]    = {32, (cuuint32_t)hi};
    cuuint32_t boxL[2]    = {32, (cuuint32_t)lo};
    enc(&g_mapHi, CU_TENSOR_MAP_DATA_TYPE_FLOAT32, 2, (void*)x,
        dims, strides, boxH, elem,
        CU_TENSOR_MAP_INTERLEAVE_NONE, CU_TENSOR_MAP_SWIZZLE_128B,
        CU_TENSOR_MAP_L2_PROMOTION_L2_256B, CU_TENSOR_MAP_FLOAT_OOB_FILL_NONE);
    enc(&g_mapLo, CU_TENSOR_MAP_DATA_TYPE_FLOAT32, 2, (void*)x,
        dims, strides, boxL, elem,
        CU_TENSOR_MAP_INTERLEAVE_NONE, CU_TENSOR_MAP_SWIZZLE_128B,
        CU_TENSOR_MAP_L2_PROMOTION_L2_256B, CU_TENSOR_MAP_FLOAT_OOB_FILL_NONE);
}

extern "C" void kernel_launch(void* const* d_in, const int* in_sizes, int n_in,
                              void* d_out, int out_size)
{
    const float* x = (const float*)d_in[0];
    const float* W = (const float*)d_in[1];
    const float* b = (const float*)d_in[2];
    float* out = (float*)d_out;

    const int n_tok = in_sizes[0] / D_MODEL;     // 16384

    if (g_nsm == 0) {
        cudaDeviceProp prop;
        cudaGetDeviceProperties(&prop, 0);
        g_nsm = prop.multiProcessorCount;        // 152 on GB300
        g_hi = (n_tok + g_nsm - 1) / g_nsm;      // 108
        g_smem = (NSTAGE * STAGE_F + 16384) * 4 + 64;
        cudaFuncSetAttribute(top2_router_kernel,
                             cudaFuncAttributeMaxDynamicSharedMemorySize, g_smem);
        build_maps(x, n_tok, g_hi, g_hi - 1);
        g_last_x = x;
    } else if (g_last_x != x) {
        build_maps(x, n_tok, g_hi, g_hi - 1);
        g_last_x = x;
    }

    top2_router_kernel<<<g_nsm, THREADS, g_smem>>>(g_mapHi, g_mapLo,
                                                   W, b, out, n_tok, g_hi);
}